// round 6
// baseline (speedup 1.0000x reference)
#include <cuda_runtime.h>
#include <cuda_bf16.h>

#define G_MAX 128
#define BLOCK 256
#define SPLIT 4   // lanes per proposal; each scans G/SPLIT gt boxes

__global__ __launch_bounds__(BLOCK)
void roi_match_kernel(const float4* __restrict__ props,
                      const float4* __restrict__ gt,
                      const int*    __restrict__ gtl32,   // gt labels, i32 or i64 (auto-detect)
                      float*        __restrict__ out_labels,
                      float4*       __restrict__ out_boxes,
                      int N, int G)
{
    __shared__ float4 s_gt[G_MAX];
    __shared__ float  s_area[G_MAX];
    __shared__ float  s_lab[G_MAX];

    const int t = threadIdx.x;
    if (t < G) {
        float4 b = gt[t];
        s_gt[t]   = b;
        s_area[t] = __fmul_rn(__fsub_rn(b.z, b.x), __fsub_rn(b.w, b.y));
        // labels >= 1, so little-endian i64 => word 1 (hi word of elem 0) == 0
        int is64 = (gtl32[1] == 0) ? 1 : 0;
        s_lab[t] = (float)gtl32[is64 ? (2 * t) : t];
    }
    __syncthreads();

    const int part = t & (SPLIT - 1);                 // which gt quarter
    const int n    = blockIdx.x * (BLOCK / SPLIT) + (t >> 2);
    const int ni   = (n < N) ? n : (N - 1);           // clamp (N%64==0 -> never taken)

    const float4 p = props[ni];
    const float parea = __fmul_rn(__fsub_rn(p.z, p.x), __fsub_rn(p.w, p.y));

    // Sentinel (bestI=0, bestS=1): first comparison reduces to inter > 0.
    float bestI = 0.0f, bestS = 1.0f;
    const int gs = part * (G / SPLIT);
    int bestIdx = gs;

    #pragma unroll 8
    for (int k = 0; k < G / SPLIT; ++k) {
        const int g = gs + k;
        const float4 gb = s_gt[g];
        float x1 = fmaxf(gb.x, p.x);
        float y1 = fmaxf(gb.y, p.y);
        float x2 = fminf(gb.z, p.z);
        float y2 = fminf(gb.w, p.w);
        float dx = fmaxf(__fsub_rn(x2, x1), 0.0f);
        float dy = fmaxf(__fsub_rn(y2, y1), 0.0f);
        float inter = __fmul_rn(dx, dy);
        float S     = __fadd_rn(s_area[g], parea);    // area_g + parea
        // iou = inter/(S - inter) monotone in inter/S (S > 0):
        //   i1/(S1-i1) > i2/(S2-i2)  <=>  i1*S2 > i2*S1  (cross terms cancel).
        // FFMA sign of the cross-difference (~1 ulp of exact); strict > keeps
        // the earlier index, matching jnp.argmax first-max semantics.
        float d = __fmaf_rn(inter, bestS, -__fmul_rn(bestI, S));
        bool take = d > 0.0f;
        bestI   = take ? inter : bestI;
        bestS   = take ? S     : bestS;
        bestIdx = take ? g     : bestIdx;
    }

    // Tree merge across the 4 lanes sharing this proposal. Tie-safe rule:
    // take partner iff strictly greater, or exactly tied with a lower index —
    // every lane then holds the first-max of the merged range, so the xor
    // exchange pattern is order-correct at both stages.
    #pragma unroll
    for (int m = 1; m < SPLIT; m <<= 1) {
        float oI   = __shfl_xor_sync(0xffffffffu, bestI,   m);
        float oS   = __shfl_xor_sync(0xffffffffu, bestS,   m);
        int   oIdx = __shfl_xor_sync(0xffffffffu, bestIdx, m);
        float dm = __fmaf_rn(oI, bestS, -__fmul_rn(bestI, oS));
        bool take = (dm > 0.0f) || (dm == 0.0f && oIdx < bestIdx);
        bestI   = take ? oI   : bestI;
        bestS   = take ? oS   : bestS;
        bestIdx = take ? oIdx : bestIdx;
    }

    if (part == 0 && n < N) {
        // uni = fl(bestS - bestI) == reference's fl(fl(a1+a2) - inter);
        // single IEEE division -> bitwise-equal iou for the winning pair.
        float uni = __fsub_rn(bestS, bestI);
        float iou = __fdiv_rn(bestI, uni);
        float lab = s_lab[bestIdx];
        if (iou < 0.5f) lab = (iou >= 0.1f) ? 0.0f : -1.0f;
        if (out_labels) out_labels[n] = lab;
        if (out_boxes)  out_boxes[n]  = s_gt[bestIdx];
    }
}

extern "C" void kernel_launch(void* const* d_in, const int* in_sizes, int n_in,
                              void* d_out, int out_size)
{
    const float4* props = (const float4*)d_in[0];
    const float4* gt    = (const float4*)d_in[1];
    const int*    gtl   = (const int*)d_in[2];

    const int N = in_sizes[0] / 4;
    const int G = in_sizes[1] / 4;

    float*  out       = (float*)d_out;
    float*  out_label = nullptr;
    float4* out_boxes = nullptr;

    if (out_size == 5 * N) {            // [labels (N) ; boxes (4N)] as f32
        out_label = out;
        out_boxes = (float4*)(out + N); // 16B-aligned since N % 4 == 0
    } else if (out_size == 4 * N) {     // boxes only
        out_boxes = (float4*)out;
    } else {                            // labels only
        out_label = out;
    }

    const int props_per_block = BLOCK / SPLIT;
    const int grid = (N + props_per_block - 1) / props_per_block;
    roi_match_kernel<<<grid, BLOCK>>>(props, gt, gtl, out_label, out_boxes, N, G);
}

// round 7
// speedup vs baseline: 2.3908x; 2.3908x over previous
#include <cuda_runtime.h>
#include <cuda_bf16.h>

#define G_MAX 128
#define BLOCK 256

// Tournament node: take the right (HIGHER-index) candidate only if strictly
// greater under the exact cross-comparison
//   Ir/(Sr-Ir) > Il/(Sl-Il)  <=>  Ir*Sl > Il*Sr   (S > I >= 0, cross terms cancel)
// FFMA gives the sign of the cross-difference to ~1 ulp; ties keep the left
// (lower-index) operand, so first-max propagates (jnp.argmax semantics).
__device__ __forceinline__ void tnode(float& Il, float& Sl, int& il,
                                      float Ir, float Sr, int ir)
{
    float d = __fmaf_rn(Ir, Sl, -__fmul_rn(Il, Sr));
    bool take = d > 0.0f;
    Il = take ? Ir : Il;
    Sl = take ? Sr : Sl;
    il = take ? ir : il;
}

__global__ __launch_bounds__(BLOCK)
void roi_match_kernel(const float4* __restrict__ props,
                      const float4* __restrict__ gt,
                      const int*    __restrict__ gtl32,   // gt labels, i32 or i64 (auto-detect)
                      float*        __restrict__ out_labels,
                      float4*       __restrict__ out_boxes,
                      int N, int G)
{
    __shared__ float4 s_gt[G_MAX];
    __shared__ float  s_area[G_MAX];
    __shared__ float  s_lab[G_MAX];

    const int t = threadIdx.x;
    if (t < G) {
        float4 b = gt[t];
        s_gt[t]   = b;
        s_area[t] = __fmul_rn(__fsub_rn(b.z, b.x), __fsub_rn(b.w, b.y));
        // labels >= 1, so little-endian i64 => word 1 (hi word of elem 0) == 0
        int is64 = (gtl32[1] == 0) ? 1 : 0;
        s_lab[t] = (float)gtl32[is64 ? (2 * t) : t];
    }
    __syncthreads();

    const int n  = blockIdx.x * BLOCK + t;
    const int ni = (n < N) ? n : (N - 1);     // clamp tail loads; store guarded

    const float4 p = props[ni];
    const float parea = __fmul_rn(__fsub_rn(p.z, p.x), __fsub_rn(p.w, p.y));

    // Sentinel: bestI=0, bestS=1 -> first strict comparison reduces to inter>0;
    // an all-zero row yields idx 0, iou = 0/(1-0) = 0 -> label -1, box gt[0],
    // matching jnp.argmax-of-zeros.
    float bestI = 0.0f, bestS = 1.0f;
    int bestIdx = 0;

    // G assumed multiple of 8 (G=128). All lanes read the SAME s_gt address ->
    // pure LDS broadcast, conflict-free.
    #pragma unroll 1
    for (int g0 = 0; g0 < G; g0 += 8) {
        float I[8], S[8];
        #pragma unroll
        for (int k = 0; k < 8; ++k) {
            const float4 gb = s_gt[g0 + k];
            float x1 = fmaxf(gb.x, p.x);
            float y1 = fmaxf(gb.y, p.y);
            float x2 = fminf(gb.z, p.z);
            float y2 = fminf(gb.w, p.w);
            float dx = fmaxf(__fsub_rn(x2, x1), 0.0f);
            float dy = fmaxf(__fsub_rn(y2, y1), 0.0f);
            I[k] = __fmul_rn(dx, dy);                      // intersection
            S[k] = __fadd_rn(s_area[g0 + k], parea);       // area_g + parea
        }

        // 3-level tournament over the 8 independent candidates (7 nodes),
        // then a single best-update: carried dependency = 1 node per 8 boxes.
        int i0 = g0,     i2 = g0 + 2, i4 = g0 + 4, i6 = g0 + 6;
        tnode(I[0], S[0], i0, I[1], S[1], g0 + 1);
        tnode(I[2], S[2], i2, I[3], S[3], g0 + 3);
        tnode(I[4], S[4], i4, I[5], S[5], g0 + 5);
        tnode(I[6], S[6], i6, I[7], S[7], g0 + 7);
        tnode(I[0], S[0], i0, I[2], S[2], i2);
        tnode(I[4], S[4], i4, I[6], S[6], i6);
        tnode(I[0], S[0], i0, I[4], S[4], i4);
        // best holds lower indices than this block -> strict > keeps first-max
        tnode(bestI, bestS, bestIdx, I[0], S[0], i0);
    }

    if (n < N) {
        // uni = fl(bestS - bestI) == reference's fl(fl(a1+a2) - inter);
        // single IEEE division -> bitwise-equal iou for the winning pair.
        float uni = __fsub_rn(bestS, bestI);
        float iou = __fdiv_rn(bestI, uni);
        float lab = s_lab[bestIdx];
        if (iou < 0.5f) lab = (iou >= 0.1f) ? 0.0f : -1.0f;
        if (out_labels) out_labels[n] = lab;
        if (out_boxes)  out_boxes[n]  = s_gt[bestIdx];
    }
}

extern "C" void kernel_launch(void* const* d_in, const int* in_sizes, int n_in,
                              void* d_out, int out_size)
{
    const float4* props = (const float4*)d_in[0];
    const float4* gt    = (const float4*)d_in[1];
    const int*    gtl   = (const int*)d_in[2];

    const int N = in_sizes[0] / 4;
    const int G = in_sizes[1] / 4;

    float*  out       = (float*)d_out;
    float*  out_label = nullptr;
    float4* out_boxes = nullptr;

    if (out_size == 5 * N) {            // [labels (N) ; boxes (4N)] as f32
        out_label = out;
        out_boxes = (float4*)(out + N); // 16B-aligned since N % 4 == 0
    } else if (out_size == 4 * N) {     // boxes only
        out_boxes = (float4*)out;
    } else {                            // labels only
        out_label = out;
    }

    const int grid = (N + BLOCK - 1) / BLOCK;
    roi_match_kernel<<<grid, BLOCK>>>(props, gt, gtl, out_label, out_boxes, N, G);
}